// round 1
// baseline (speedup 1.0000x reference)
#include <cuda_runtime.h>
#include <math.h>

#define DD 196
#define SEQ 65
#define NCH 64
#define NH 8
#define DH 64
#define INNER 512
#define MLP 784

// Scratch (allocation-free, __device__ globals)
__device__ float g_xatt[SEQ * DD];
__device__ float g_h[SEQ * DD];
__device__ float g_qkv[SEQ * 3 * INNER];
__device__ float g_o[SEQ * INNER];
__device__ float g_x2[SEQ * DD];
__device__ float g_h2[SEQ * DD];
__device__ float g_ff[SEQ * MLP];

// ---------------------------------------------------------------------------
// Kernel 1: conv1d+BN+ReLU -> sort-based gating -> FC -> sigmoid -> x_att
// single block, 256 threads
// ---------------------------------------------------------------------------
__global__ void k_gate(const float* __restrict__ x_pe, const float* __restrict__ tokens,
                       const float* __restrict__ conv_k,
                       const float* __restrict__ bn_g, const float* __restrict__ bn_b,
                       const float* __restrict__ bn_rm, const float* __restrict__ bn_rv,
                       const float* __restrict__ fc_w1, const float* __restrict__ fc_w2) {
    __shared__ float b1s[NCH];
    __shared__ float b2s[NCH];
    __shared__ float csm[NCH];
    __shared__ float hid[12];

    int t = threadIdx.x;
    int w = t >> 5, l = t & 31;

    float km0 = conv_k[3], km1 = conv_k[4], km2 = conv_k[5];  // conv_k[1][*]
    float s = bn_g[0] * rsqrtf(bn_rv[0] + 1e-5f);
    float bias = bn_b[0] - bn_rm[0] * s;

    // conv + bn + relu, store a into g_xatt rows 0..63, per-channel mean -> b1
    for (int ch = w; ch < NCH; ch += 8) {
        const float* row = x_pe + ch * DD;
        float sum = 0.f;
        for (int i = l; i < DD; i += 32) {
            float left  = (i > 0)      ? row[i - 1] : 0.f;
            float mid   = row[i];
            float right = (i < DD - 1) ? row[i + 1] : 0.f;
            float conv = km0 * left + km1 * mid + km2 * right;
            float a = fmaxf(conv * s + bias, 0.f);
            g_xatt[ch * DD + i] = a;
            sum += a;
        }
        #pragma unroll
        for (int o = 16; o; o >>= 1) sum += __shfl_xor_sync(0xffffffffu, sum, o);
        if (l == 0) b1s[ch] = sum * (1.f / DD);
    }
    __syncthreads();

    // rank / middle / b2 (exact stable-argsort semantics)
    if (t < NCH) {
        float v = b1s[t];
        int rank = 0, cnt = 0;
        float mx = -1e30f, mn = 1e30f;
        for (int j = 0; j < NCH; j++) {
            float u = b1s[j];
            rank += (u < v) || (u == v && j < t);
            cnt += (u <= 0.f);
            mx = fmaxf(mx, u);
            mn = fminf(mn, u);
        }
        // middle = argmax(sorted > 0): first positive index = #(<=0); 0 if none positive
        int middle = (cnt == NCH) ? 0 : cnt;
        if (mx < 0.f || mn > 0.f) middle = 32;
        float ls = (float)middle, le = (float)(NCH - middle);
        float o;
        if (rank < middle) o = v - 1.f / (1.f + powf(ls, v));
        else               o = v + 1.f / (1.f + powf(le, -v));
        b2s[t] = o;
    }
    __syncthreads();

    if (t < 12) {
        float acc = 0.f;
        for (int c = 0; c < NCH; c++) acc += b2s[c] * fc_w1[c * 12 + t];
        hid[t] = fmaxf(acc, 0.f);
    }
    __syncthreads();

    if (t < NCH) {
        float acc = 0.f;
        #pragma unroll
        for (int k = 0; k < 12; k++) acc += hid[k] * fc_w2[k * NCH + t];
        csm[t] = 1.f / (1.f + expf(-acc));
    }
    __syncthreads();

    for (int i = t; i < NCH * DD; i += 256) g_xatt[i] *= csm[i / DD];
    for (int i = t; i < DD; i += 256) g_xatt[NCH * DD + i] = tokens[i];
}

// ---------------------------------------------------------------------------
// LayerNorm (one block per row)
// ---------------------------------------------------------------------------
__device__ __forceinline__ void ln_row(const float* __restrict__ in,
                                       const float* __restrict__ g,
                                       const float* __restrict__ b,
                                       float* __restrict__ out) {
    int r = blockIdx.x, t = threadIdx.x;
    __shared__ float rs[8], rq[8];
    const float* row = in + r * DD;
    float sum = 0.f, sq = 0.f;
    for (int i = t; i < DD; i += 256) { float v = row[i]; sum += v; sq += v * v; }
    #pragma unroll
    for (int o = 16; o; o >>= 1) {
        sum += __shfl_xor_sync(0xffffffffu, sum, o);
        sq  += __shfl_xor_sync(0xffffffffu, sq, o);
    }
    if ((t & 31) == 0) { rs[t >> 5] = sum; rq[t >> 5] = sq; }
    __syncthreads();
    if (t < 32) {
        sum = (t < 8) ? rs[t] : 0.f;
        sq  = (t < 8) ? rq[t] : 0.f;
        #pragma unroll
        for (int o = 4; o; o >>= 1) {
            sum += __shfl_xor_sync(0xffffffffu, sum, o);
            sq  += __shfl_xor_sync(0xffffffffu, sq, o);
        }
        if (t == 0) { rs[0] = sum; rq[0] = sq; }
    }
    __syncthreads();
    float mean = rs[0] * (1.f / DD);
    float var = rq[0] * (1.f / DD) - mean * mean;
    float inv = rsqrtf(var + 1e-5f);
    for (int i = t; i < DD; i += 256)
        out[r * DD + i] = (row[i] - mean) * inv * g[i] + b[i];
}

__global__ void k_ln1(const float* __restrict__ x, const float* __restrict__ g,
                      const float* __restrict__ b) { ln_row(x, g, b, g_h); }
__global__ void k_ln2(const float* __restrict__ g, const float* __restrict__ b) {
    ln_row(g_x2, g, b, g_h2);
}

// ---------------------------------------------------------------------------
// QKV GEMM: [65,196] @ [196,1536].  grid (13, 6), 256 thr, 5 rows/block
// ---------------------------------------------------------------------------
__global__ void k_qkv(const float* __restrict__ w) {
    __shared__ float hs[5 * DD];
    int r0 = blockIdx.x * 5;
    int col = blockIdx.y * 256 + threadIdx.x;  // always < 1536
    for (int i = threadIdx.x; i < 5 * DD; i += 256) hs[i] = g_h[r0 * DD + i];
    __syncthreads();
    float acc[5] = {0.f, 0.f, 0.f, 0.f, 0.f};
    for (int k = 0; k < DD; k++) {
        float wv = w[k * 1536 + col];
        #pragma unroll
        for (int r = 0; r < 5; r++) acc[r] += hs[r * DD + k] * wv;
    }
    #pragma unroll
    for (int r = 0; r < 5; r++) g_qkv[(r0 + r) * 1536 + col] = acc[r];
}

// ---------------------------------------------------------------------------
// Attention: one block per head, K/V in smem, 32-row score chunks
// ---------------------------------------------------------------------------
__global__ void k_attn() {
    __shared__ float sk[SEQ * DH];
    __shared__ float sv[SEQ * DH];
    __shared__ float sp[32 * 66];
    int h = blockIdx.x, t = threadIdx.x;

    for (int i = t; i < SEQ * DH; i += 256) {
        int r = i >> 6, d = i & 63;
        sk[i] = g_qkv[r * 1536 + INNER + h * 64 + d];
        sv[i] = g_qkv[r * 1536 + 2 * INNER + h * 64 + d];
    }
    __syncthreads();

    for (int base = 0; base < SEQ; base += 32) {
        int nrows = min(32, SEQ - base);
        // scores
        for (int e = t; e < nrows * SEQ; e += 256) {
            int i = e / SEQ, j = e - i * SEQ;
            const float* q = g_qkv + (base + i) * 1536 + h * 64;
            float acc = 0.f;
            #pragma unroll 8
            for (int d = 0; d < DH; d++) acc += q[d] * sk[j * 64 + d];
            sp[i * 66 + j] = acc * 0.125f;
        }
        __syncthreads();
        // softmax: one warp per row
        int wrp = t >> 5, l = t & 31;
        for (int i = wrp; i < nrows; i += 8) {
            float mx = -1e30f;
            for (int j = l; j < SEQ; j += 32) mx = fmaxf(mx, sp[i * 66 + j]);
            #pragma unroll
            for (int o = 16; o; o >>= 1) mx = fmaxf(mx, __shfl_xor_sync(0xffffffffu, mx, o));
            float sum = 0.f;
            for (int j = l; j < SEQ; j += 32) {
                float p = expf(sp[i * 66 + j] - mx);
                sp[i * 66 + j] = p;
                sum += p;
            }
            #pragma unroll
            for (int o = 16; o; o >>= 1) sum += __shfl_xor_sync(0xffffffffu, sum, o);
            float inv = 1.f / sum;
            for (int j = l; j < SEQ; j += 32) sp[i * 66 + j] *= inv;
        }
        __syncthreads();
        // o = p @ v
        for (int e = t; e < nrows * DH; e += 256) {
            int i = e >> 6, d = e & 63;
            float acc = 0.f;
            for (int j = 0; j < SEQ; j++) acc += sp[i * 66 + j] * sv[j * 64 + d];
            g_o[(base + i) * INNER + h * 64 + d] = acc;
        }
        __syncthreads();
    }
}

// ---------------------------------------------------------------------------
// Out-proj + residuals: x2 = o @ w_out + b_out + x + x_att. grid 13, 256 thr
// ---------------------------------------------------------------------------
__global__ void k_oproj(const float* __restrict__ w_out, const float* __restrict__ b_out,
                        const float* __restrict__ x) {
    __shared__ float so[5 * INNER];
    int r0 = blockIdx.x * 5;
    for (int i = threadIdx.x; i < 5 * INNER; i += 256) so[i] = g_o[r0 * INNER + i];
    __syncthreads();
    int col = threadIdx.x;
    if (col < DD) {
        float acc[5] = {0.f, 0.f, 0.f, 0.f, 0.f};
        for (int k = 0; k < INNER; k++) {
            float wv = w_out[k * DD + col];
            #pragma unroll
            for (int r = 0; r < 5; r++) acc[r] += so[r * INNER + k] * wv;
        }
        float bb = b_out[col];
        #pragma unroll
        for (int r = 0; r < 5; r++) {
            int row = r0 + r;
            g_x2[row * DD + col] = acc[r] + bb + x[row * DD + col] + g_xatt[row * DD + col];
        }
    }
}

// ---------------------------------------------------------------------------
// FF1 + exact GELU: [65,196] @ [196,784]. grid (13, 4), 256 thr
// ---------------------------------------------------------------------------
__global__ void k_ff1(const float* __restrict__ w1, const float* __restrict__ b1v) {
    __shared__ float hs[5 * DD];
    int r0 = blockIdx.x * 5;
    int col = blockIdx.y * 256 + threadIdx.x;
    for (int i = threadIdx.x; i < 5 * DD; i += 256) hs[i] = g_h2[r0 * DD + i];
    __syncthreads();
    if (col < MLP) {
        float acc[5] = {0.f, 0.f, 0.f, 0.f, 0.f};
        for (int k = 0; k < DD; k++) {
            float wv = w1[k * MLP + col];
            #pragma unroll
            for (int r = 0; r < 5; r++) acc[r] += hs[r * DD + k] * wv;
        }
        float bb = b1v[col];
        #pragma unroll
        for (int r = 0; r < 5; r++) {
            float v = acc[r] + bb;
            g_ff[(r0 + r) * MLP + col] = 0.5f * v * (1.f + erff(v * 0.70710678118654752f));
        }
    }
}

// ---------------------------------------------------------------------------
// FF2 + residual: out = g_ff @ w2 + b2 + x2. grid 13, 256 thr
// ---------------------------------------------------------------------------
__global__ void k_ff2(const float* __restrict__ w2, const float* __restrict__ b2v,
                      float* __restrict__ out) {
    __shared__ float sg[5 * MLP];
    int r0 = blockIdx.x * 5;
    for (int i = threadIdx.x; i < 5 * MLP; i += 256) sg[i] = g_ff[r0 * MLP + i];
    __syncthreads();
    int col = threadIdx.x;
    if (col < DD) {
        float acc[5] = {0.f, 0.f, 0.f, 0.f, 0.f};
        for (int k = 0; k < MLP; k++) {
            float wv = w2[k * DD + col];
            #pragma unroll
            for (int r = 0; r < 5; r++) acc[r] += sg[r * MLP + k] * wv;
        }
        float bb = b2v[col];
        #pragma unroll
        for (int r = 0; r < 5; r++) {
            int row = r0 + r;
            out[row * DD + col] = acc[r] + bb + g_x2[row * DD + col];
        }
    }
}

// ---------------------------------------------------------------------------
extern "C" void kernel_launch(void* const* d_in, const int* in_sizes, int n_in,
                              void* d_out, int out_size) {
    const float* x      = (const float*)d_in[0];
    const float* tokens = (const float*)d_in[1];
    const float* x_pe   = (const float*)d_in[2];
    const float* conv_k = (const float*)d_in[3];
    const float* bn_g   = (const float*)d_in[4];
    const float* bn_b   = (const float*)d_in[5];
    const float* bn_rm  = (const float*)d_in[6];
    const float* bn_rv  = (const float*)d_in[7];
    const float* fc_w1  = (const float*)d_in[8];
    const float* fc_w2  = (const float*)d_in[9];
    const float* ln1_g  = (const float*)d_in[10];
    const float* ln1_b  = (const float*)d_in[11];
    const float* ln2_g  = (const float*)d_in[12];
    const float* ln2_b  = (const float*)d_in[13];
    const float* w_qkv  = (const float*)d_in[14];
    const float* w_out  = (const float*)d_in[15];
    const float* b_out  = (const float*)d_in[16];
    const float* ff_w1  = (const float*)d_in[17];
    const float* ff_b1  = (const float*)d_in[18];
    const float* ff_w2  = (const float*)d_in[19];
    const float* ff_b2  = (const float*)d_in[20];
    float* out = (float*)d_out;

    k_gate<<<1, 256>>>(x_pe, tokens, conv_k, bn_g, bn_b, bn_rm, bn_rv, fc_w1, fc_w2);
    k_ln1<<<SEQ, 256>>>(x, ln1_g, ln1_b);
    k_qkv<<<dim3(13, 6), 256>>>(w_qkv);
    k_attn<<<NH, 256>>>();
    k_oproj<<<13, 256>>>(w_out, b_out, x);
    k_ln2<<<SEQ, 256>>>(ln2_g, ln2_b);
    k_ff1<<<dim3(13, 4), 256>>>(ff_w1, ff_b1);
    k_ff2<<<13, 256>>>(ff_w2, ff_b2, out);
}

// round 2
// speedup vs baseline: 2.6094x; 2.6094x over previous
#include <cuda_runtime.h>
#include <math.h>

#define DD 196
#define SEQ 65
#define NCH 64
#define NH 8
#define DH 64
#define INNER 512
#define MLP 784

// Scratch (allocation-free, __device__ globals)
__device__ float g_xatt[SEQ * DD];
__device__ float g_qkv[SEQ * 3 * INNER];
__device__ float g_o[SEQ * INNER];
__device__ float g_x2[SEQ * DD];
__device__ float g_ff[SEQ * MLP];

// ---------------------------------------------------------------------------
// Kernel 1: conv1d+BN+ReLU -> sort-based gating -> FC -> sigmoid -> x_att
// single block, 256 threads
// ---------------------------------------------------------------------------
__global__ void k_gate(const float* __restrict__ x_pe, const float* __restrict__ tokens,
                       const float* __restrict__ conv_k,
                       const float* __restrict__ bn_g, const float* __restrict__ bn_b,
                       const float* __restrict__ bn_rm, const float* __restrict__ bn_rv,
                       const float* __restrict__ fc_w1, const float* __restrict__ fc_w2) {
    __shared__ float b1s[NCH];
    __shared__ float b2s[NCH];
    __shared__ float csm[NCH];
    __shared__ float hid[12];

    int t = threadIdx.x;
    int w = t >> 5, l = t & 31;

    float km0 = conv_k[3], km1 = conv_k[4], km2 = conv_k[5];  // conv_k[1][*]
    float s = bn_g[0] * rsqrtf(bn_rv[0] + 1e-5f);
    float bias = bn_b[0] - bn_rm[0] * s;

    for (int ch = w; ch < NCH; ch += 8) {
        const float* row = x_pe + ch * DD;
        float sum = 0.f;
        for (int i = l; i < DD; i += 32) {
            float left  = (i > 0)      ? row[i - 1] : 0.f;
            float mid   = row[i];
            float right = (i < DD - 1) ? row[i + 1] : 0.f;
            float conv = km0 * left + km1 * mid + km2 * right;
            float a = fmaxf(conv * s + bias, 0.f);
            g_xatt[ch * DD + i] = a;
            sum += a;
        }
        #pragma unroll
        for (int o = 16; o; o >>= 1) sum += __shfl_xor_sync(0xffffffffu, sum, o);
        if (l == 0) b1s[ch] = sum * (1.f / DD);
    }
    __syncthreads();

    if (t < NCH) {
        float v = b1s[t];
        int rank = 0, cnt = 0;
        float mx = -1e30f, mn = 1e30f;
        for (int j = 0; j < NCH; j++) {
            float u = b1s[j];
            rank += (u < v) || (u == v && j < t);
            cnt += (u <= 0.f);
            mx = fmaxf(mx, u);
            mn = fminf(mn, u);
        }
        int middle = (cnt == NCH) ? 0 : cnt;
        if (mx < 0.f || mn > 0.f) middle = 32;
        float ls = (float)middle, le = (float)(NCH - middle);
        float o;
        if (rank < middle) o = v - 1.f / (1.f + powf(ls, v));
        else               o = v + 1.f / (1.f + powf(le, -v));
        b2s[t] = o;
    }
    __syncthreads();

    if (t < 12) {
        float acc = 0.f;
        for (int c = 0; c < NCH; c++) acc += b2s[c] * fc_w1[c * 12 + t];
        hid[t] = fmaxf(acc, 0.f);
    }
    __syncthreads();

    if (t < NCH) {
        float acc = 0.f;
        #pragma unroll
        for (int k = 0; k < 12; k++) acc += hid[k] * fc_w2[k * NCH + t];
        csm[t] = 1.f / (1.f + expf(-acc));
    }
    __syncthreads();

    for (int i = t; i < NCH * DD; i += 256) g_xatt[i] *= csm[i / DD];
    for (int i = t; i < DD; i += 256) g_xatt[NCH * DD + i] = tokens[i];
}

// ---------------------------------------------------------------------------
// In-block LayerNorm over a 5-row tile held in smem.
// xs: 5*DD input rows; hs: 5*DD normalized output. 256 threads.
// ---------------------------------------------------------------------------
__device__ __forceinline__ void ln_tile(const float* __restrict__ xs,
                                        float* __restrict__ hs,
                                        const float* __restrict__ g,
                                        const float* __restrict__ b,
                                        float* __restrict__ smean,
                                        float* __restrict__ sinv) {
    int t = threadIdx.x, w = t >> 5, l = t & 31;
    if (w < 5) {
        float sum = 0.f, sq = 0.f;
        for (int i = l; i < DD; i += 32) {
            float v = xs[w * DD + i];
            sum += v; sq += v * v;
        }
        #pragma unroll
        for (int o = 16; o; o >>= 1) {
            sum += __shfl_xor_sync(0xffffffffu, sum, o);
            sq  += __shfl_xor_sync(0xffffffffu, sq, o);
        }
        if (l == 0) {
            float mean = sum * (1.f / DD);
            float var = sq * (1.f / DD) - mean * mean;
            smean[w] = mean;
            sinv[w] = rsqrtf(var + 1e-5f);
        }
    }
    __syncthreads();
    for (int i = t; i < 5 * DD; i += 256) {
        int r = i / DD, c = i - r * DD;
        hs[i] = (xs[i] - smean[r]) * sinv[r] * g[c] + b[c];
    }
    __syncthreads();
}

// ---------------------------------------------------------------------------
// LN1 + QKV GEMM: [65,196] @ [196,1536]. grid (13, 6), 256 thr, 5 rows/block
// ---------------------------------------------------------------------------
__global__ void k_qkv(const float* __restrict__ x, const float* __restrict__ ln_g,
                      const float* __restrict__ ln_b, const float* __restrict__ w) {
    __shared__ float xs[5 * DD];
    __shared__ float hs[5 * DD];
    __shared__ float smean[5], sinv[5];
    int r0 = blockIdx.x * 5;
    int col = blockIdx.y * 256 + threadIdx.x;  // always < 1536
    for (int i = threadIdx.x; i < 5 * DD; i += 256) xs[i] = x[r0 * DD + i];
    __syncthreads();
    ln_tile(xs, hs, ln_g, ln_b, smean, sinv);
    float acc[5] = {0.f, 0.f, 0.f, 0.f, 0.f};
    for (int k = 0; k < DD; k++) {
        float wv = w[k * 1536 + col];
        #pragma unroll
        for (int r = 0; r < 5; r++) acc[r] += hs[r * DD + k] * wv;
    }
    #pragma unroll
    for (int r = 0; r < 5; r++) g_qkv[(r0 + r) * 1536 + col] = acc[r];
}

// ---------------------------------------------------------------------------
// Attention: grid (13 row-tiles, 8 heads), 160 threads.
// K stored transposed with stride 67 (conflict-free score reads).
// ---------------------------------------------------------------------------
__global__ void k_attn() {
    __shared__ float skT[DH * 67];       // [d][j]
    __shared__ float sv[SEQ * DH];       // [j][d]
    __shared__ float sq[5 * DH];
    __shared__ float sp[5 * 66];
    int h = blockIdx.y, r0 = blockIdx.x * 5;
    int t = threadIdx.x;

    for (int i = t; i < SEQ * DH; i += 160) {
        int j = i >> 6, d = i & 63;
        skT[d * 67 + j] = g_qkv[j * 1536 + INNER + h * 64 + d];
        sv[i]           = g_qkv[j * 1536 + 2 * INNER + h * 64 + d];
    }
    for (int i = t; i < 5 * DH; i += 160) {
        int r = i >> 6, d = i & 63;
        sq[i] = g_qkv[(r0 + r) * 1536 + h * 64 + d];
    }
    __syncthreads();

    // scores: 5x65 elements
    for (int e = t; e < 5 * SEQ; e += 160) {
        int i = e / SEQ, j = e - i * SEQ;
        float acc = 0.f;
        #pragma unroll
        for (int d = 0; d < DH; d++) acc += sq[i * 64 + d] * skT[d * 67 + j];
        sp[i * 66 + j] = acc * 0.125f;
    }
    __syncthreads();

    // softmax: warp per row
    int w = t >> 5, l = t & 31;
    if (w < 5) {
        float mx = -1e30f;
        for (int j = l; j < SEQ; j += 32) mx = fmaxf(mx, sp[w * 66 + j]);
        #pragma unroll
        for (int o = 16; o; o >>= 1) mx = fmaxf(mx, __shfl_xor_sync(0xffffffffu, mx, o));
        float sum = 0.f;
        for (int j = l; j < SEQ; j += 32) {
            float p = expf(sp[w * 66 + j] - mx);
            sp[w * 66 + j] = p;
            sum += p;
        }
        #pragma unroll
        for (int o = 16; o; o >>= 1) sum += __shfl_xor_sync(0xffffffffu, sum, o);
        float inv = 1.f / sum;
        for (int j = l; j < SEQ; j += 32) sp[w * 66 + j] *= inv;
    }
    __syncthreads();

    // o = p @ v : 5x64 elements
    for (int e = t; e < 5 * DH; e += 160) {
        int i = e >> 6, d = e & 63;
        float acc = 0.f;
        #pragma unroll 5
        for (int j = 0; j < SEQ; j++) acc += sp[i * 66 + j] * sv[j * 64 + d];
        g_o[(r0 + i) * INNER + h * 64 + d] = acc;
    }
}

// ---------------------------------------------------------------------------
// Out-proj + residuals: x2 = o @ w_out + b_out + x + x_att. grid 13, 256 thr
// ---------------------------------------------------------------------------
__global__ void k_oproj(const float* __restrict__ w_out, const float* __restrict__ b_out,
                        const float* __restrict__ x) {
    __shared__ float so[5 * INNER];
    int r0 = blockIdx.x * 5;
    for (int i = threadIdx.x; i < 5 * INNER; i += 256) so[i] = g_o[r0 * INNER + i];
    __syncthreads();
    int col = threadIdx.x;
    if (col < DD) {
        float acc[5] = {0.f, 0.f, 0.f, 0.f, 0.f};
        for (int k = 0; k < INNER; k++) {
            float wv = w_out[k * DD + col];
            #pragma unroll
            for (int r = 0; r < 5; r++) acc[r] += so[r * INNER + k] * wv;
        }
        float bb = b_out[col];
        #pragma unroll
        for (int r = 0; r < 5; r++) {
            int row = r0 + r;
            g_x2[row * DD + col] = acc[r] + bb + x[row * DD + col] + g_xatt[row * DD + col];
        }
    }
}

// ---------------------------------------------------------------------------
// LN2 + FF1 + exact GELU: [65,196] @ [196,784]. grid (13, 4), 256 thr
// ---------------------------------------------------------------------------
__global__ void k_ff1(const float* __restrict__ ln_g, const float* __restrict__ ln_b,
                      const float* __restrict__ w1, const float* __restrict__ b1v) {
    __shared__ float xs[5 * DD];
    __shared__ float hs[5 * DD];
    __shared__ float smean[5], sinv[5];
    int r0 = blockIdx.x * 5;
    int col = blockIdx.y * 256 + threadIdx.x;
    for (int i = threadIdx.x; i < 5 * DD; i += 256) xs[i] = g_x2[r0 * DD + i];
    __syncthreads();
    ln_tile(xs, hs, ln_g, ln_b, smean, sinv);
    if (col < MLP) {
        float acc[5] = {0.f, 0.f, 0.f, 0.f, 0.f};
        for (int k = 0; k < DD; k++) {
            float wv = w1[k * MLP + col];
            #pragma unroll
            for (int r = 0; r < 5; r++) acc[r] += hs[r * DD + k] * wv;
        }
        float bb = b1v[col];
        #pragma unroll
        for (int r = 0; r < 5; r++) {
            float v = acc[r] + bb;
            g_ff[(r0 + r) * MLP + col] = 0.5f * v * (1.f + erff(v * 0.70710678118654752f));
        }
    }
}

// ---------------------------------------------------------------------------
// FF2 + residual: out = g_ff @ w2 + b2 + x2. grid 13, 256 thr
// ---------------------------------------------------------------------------
__global__ void k_ff2(const float* __restrict__ w2, const float* __restrict__ b2v,
                      float* __restrict__ out) {
    __shared__ float sg[5 * MLP];
    int r0 = blockIdx.x * 5;
    for (int i = threadIdx.x; i < 5 * MLP; i += 256) sg[i] = g_ff[r0 * MLP + i];
    __syncthreads();
    int col = threadIdx.x;
    if (col < DD) {
        float acc[5] = {0.f, 0.f, 0.f, 0.f, 0.f};
        for (int k = 0; k < MLP; k++) {
            float wv = w2[k * DD + col];
            #pragma unroll
            for (int r = 0; r < 5; r++) acc[r] += sg[r * MLP + k] * wv;
        }
        float bb = b2v[col];
        #pragma unroll
        for (int r = 0; r < 5; r++) {
            int row = r0 + r;
            out[row * DD + col] = acc[r] + bb + g_x2[row * DD + col];
        }
    }
}

// ---------------------------------------------------------------------------
extern "C" void kernel_launch(void* const* d_in, const int* in_sizes, int n_in,
                              void* d_out, int out_size) {
    const float* x      = (const float*)d_in[0];
    const float* tokens = (const float*)d_in[1];
    const float* x_pe   = (const float*)d_in[2];
    const float* conv_k = (const float*)d_in[3];
    const float* bn_g   = (const float*)d_in[4];
    const float* bn_b   = (const float*)d_in[5];
    const float* bn_rm  = (const float*)d_in[6];
    const float* bn_rv  = (const float*)d_in[7];
    const float* fc_w1  = (const float*)d_in[8];
    const float* fc_w2  = (const float*)d_in[9];
    const float* ln1_g  = (const float*)d_in[10];
    const float* ln1_b  = (const float*)d_in[11];
    const float* ln2_g  = (const float*)d_in[12];
    const float* ln2_b  = (const float*)d_in[13];
    const float* w_qkv  = (const float*)d_in[14];
    const float* w_out  = (const float*)d_in[15];
    const float* b_out  = (const float*)d_in[16];
    const float* ff_w1  = (const float*)d_in[17];
    const float* ff_b1  = (const float*)d_in[18];
    const float* ff_w2  = (const float*)d_in[19];
    const float* ff_b2  = (const float*)d_in[20];
    float* out = (float*)d_out;

    k_gate<<<1, 256>>>(x_pe, tokens, conv_k, bn_g, bn_b, bn_rm, bn_rv, fc_w1, fc_w2);
    k_qkv<<<dim3(13, 6), 256>>>(x, ln1_g, ln1_b, w_qkv);
    k_attn<<<dim3(13, NH), 160>>>();
    k_oproj<<<13, 256>>>(w_out, b_out, x);
    k_ff1<<<dim3(13, 4), 256>>>(ln2_g, ln2_b, ff_w1, ff_b1);
    k_ff2<<<13, 256>>>(ff_w2, ff_b2, out);
}